// round 10
// baseline (speedup 1.0000x reference)
#include <cuda_runtime.h>
#include <cuda_fp16.h>
#include <cstdint>

#define M_TOK 64
#define N_OUT 8192
#define K_IN  8192
#define NG    64            // K groups per row (8192/128)
#define NTILES (N_OUT / 64) // 128
#define WTOTAL (NTILES * NG)// 8192 work units
#define NCTA  296           // 2 per SM on 148 SMs
#define BN    64
#define BK    128
#define LDK   136           // Bs row stride in halves (padded, conflict-free ldmatrix)
#define NTHREADS 256
#define RAWSTG 32768        // 64 rows * 512 B raw int32 weights per stage
#define ASTG   16384        // 64 rows * 256 B x-halves per stage (XOR swizzle, no pad)
#define BS_BYTES (BN * LDK * 2)                    // 17408
#define SMEM_BYTES (2 * RAWSTG + 2 * ASTG + BS_BYTES)  // 115712 B -> 2 CTA/SM

__device__ __half   g_xh[M_TOK * K_IN];      // x in fp16 (1 MB, L2-resident)
__device__ uint32_t g_szp[NG * N_OUT];       // packed (s,z) half2 (2 MB)
__device__ float    g_part[NCTA * 2 * 4096]; // stream-K partials

__device__ __forceinline__ int gsplit(int c) { return (int)(((long long)c * WTOTAL) / NCTA); }

// ---- prep: convert x to fp16 + pack (s,z) to half2 ----
__global__ void prep_kernel(const float* __restrict__ x, const float* __restrict__ sz) {
    const int NX = M_TOK * K_IN / 8;
    int t = blockIdx.x * blockDim.x + threadIdx.x;
    if (t < NX) {
        float4 v0 = *reinterpret_cast<const float4*>(x + (size_t)t * 8);
        float4 v1 = *reinterpret_cast<const float4*>(x + (size_t)t * 8 + 4);
        __half2 h0 = __floats2half2_rn(v0.x, v0.y);
        __half2 h1 = __floats2half2_rn(v0.z, v0.w);
        __half2 h2 = __floats2half2_rn(v1.x, v1.y);
        __half2 h3 = __floats2half2_rn(v1.z, v1.w);
        uint4 pk;
        pk.x = *reinterpret_cast<uint32_t*>(&h0);
        pk.y = *reinterpret_cast<uint32_t*>(&h1);
        pk.z = *reinterpret_cast<uint32_t*>(&h2);
        pk.w = *reinterpret_cast<uint32_t*>(&h3);
        *reinterpret_cast<uint4*>(g_xh + (size_t)t * 8) = pk;
    } else {
        int u = t - NX;
        float4 v0 = *reinterpret_cast<const float4*>(sz + (size_t)u * 8);
        float4 v1 = *reinterpret_cast<const float4*>(sz + (size_t)u * 8 + 4);
        __half2 a = __floats2half2_rn(v0.x, v0.y);
        __half2 b = __floats2half2_rn(v0.z, v0.w);
        __half2 c2 = __floats2half2_rn(v1.x, v1.y);
        __half2 d = __floats2half2_rn(v1.z, v1.w);
        uint4 pk;
        pk.x = *reinterpret_cast<uint32_t*>(&a);
        pk.y = *reinterpret_cast<uint32_t*>(&b);
        pk.z = *reinterpret_cast<uint32_t*>(&c2);
        pk.w = *reinterpret_cast<uint32_t*>(&d);
        *reinterpret_cast<uint4*>(g_szp + (size_t)u * 4) = pk;
    }
}

// ---- stream-K reduce ----
__global__ void reduce_kernel(float* __restrict__ out) {
    int i2 = (blockIdx.x * blockDim.x + threadIdx.x) * 2;
    int m  = i2 >> 13;
    int n  = i2 & (N_OUT - 1);
    int nt = n >> 6, nl = n & 63;
    int X  = nt << 6;
    int c  = (int)(((long long)X * NCTA) >> 13);
    while (gsplit(c + 1) <= X) ++c;
    float sx = 0.f, sy = 0.f;
    while (c < NCTA && gsplit(c) < X + 64) {
        int seg = ((gsplit(c) >> 6) == nt) ? 0 : 1;
        const float2 v = *reinterpret_cast<const float2*>(
            g_part + ((size_t)c * 2 + seg) * 4096 + m * 64 + nl);
        sx += v.x; sy += v.y;
        ++c;
    }
    *reinterpret_cast<float2*>(out + i2) = make_float2(sx, sy);
}

__device__ __forceinline__ void cp16(uint32_t dst, const void* src) {
    asm volatile("cp.async.cg.shared.global [%0], [%1], 16;" :: "r"(dst), "l"(src));
}
__device__ __forceinline__ void lds128(uint4& v, uint32_t a) {
    asm volatile("ld.shared.v4.u32 {%0,%1,%2,%3}, [%4];"
                 : "=r"(v.x), "=r"(v.y), "=r"(v.z), "=r"(v.w) : "r"(a));
}
__device__ __forceinline__ void ldsm4(uint32_t& r0, uint32_t& r1, uint32_t& r2, uint32_t& r3,
                                      uint32_t a) {
    asm volatile("ldmatrix.sync.aligned.m8n8.x4.shared.b16 {%0,%1,%2,%3}, [%4];"
                 : "=r"(r0), "=r"(r1), "=r"(r2), "=r"(r3) : "r"(a));
}
__device__ __forceinline__ void mma_16816(float c[4],
                                          uint32_t a0, uint32_t a1, uint32_t a2, uint32_t a3,
                                          uint32_t b0, uint32_t b1) {
    asm volatile("mma.sync.aligned.m16n8k16.row.col.f32.f16.f16.f32 "
                 "{%0,%1,%2,%3}, {%4,%5,%6,%7}, {%8,%9}, {%0,%1,%2,%3};"
                 : "+f"(c[0]), "+f"(c[1]), "+f"(c[2]), "+f"(c[3])
                 : "r"(a0), "r"(a1), "r"(a2), "r"(a3), "r"(b0), "r"(b1));
}

__global__ void __launch_bounds__(NTHREADS, 2)
woq_gemm_kernel(const int* __restrict__ qw)
{
    extern __shared__ char smem[];
    const uint32_t s_base = (uint32_t)__cvta_generic_to_shared(smem);
    const uint32_t rawb = s_base;                    // 2 * RAWSTG
    const uint32_t asb  = s_base + 2 * RAWSTG;       // 2 * ASTG
    const uint32_t bsb  = s_base + 2 * RAWSTG + 2 * ASTG;  // BS_BYTES
    __half* Bs = reinterpret_cast<__half*>(smem + 2 * RAWSTG + 2 * ASTG);

    const int tid  = threadIdx.x;
    const int lane = tid & 31;
    const int warp = tid >> 5;
    const int wm   = warp & 3;
    const int wn   = warp >> 2;
    const int cta  = blockIdx.x;

    const int w0 = gsplit(cta);
    const int w1 = gsplit(cta + 1);
    const int nb = 0;  // per-w below

    float acc[4][4];
    #pragma unroll
    for (int i = 0; i < 4; ++i)
        #pragma unroll
        for (int j = 0; j < 4; ++j) acc[i][j] = 0.f;

    // ---- cp.async mappings ----
    // raw: thread r = tid>>2 (row), 8 units u = (tid&3)*8 + j
    const int rrow = tid >> 2;
    const int ru0  = (tid & 3) * 8;
    // x: thread r = tid>>2 (row), 4 units u = (tid&3)*4 + j, XOR swizzle u^(r&7)
    const int xrow = tid >> 2;
    const int xu0  = (tid & 3) * 4;

    // Bs ldmatrix addressing (single buffer)
    const uint32_t b_off0 = bsb + 2u * ((wn * 32 + (lane & 7) + ((lane >> 4) << 3)) * LDK
                                        + ((lane >> 3) & 1) * 8);
    const uint32_t b_off1 = b_off0 + 2u * 16 * LDK;
    // As ldmatrix row params (swizzled per-kk)
    const int a_row = wm * 16 + (lane & 15);
    const int a_hi  = lane >> 4;
    const int a_sw  = a_row & 7;
    const uint32_t a_rowb = asb + (uint32_t)a_row * 256;

    // dequant LDS base: row = it*8+warp, 16B at lane*16
    const uint32_t d_base = rawb + (uint32_t)warp * 512 + lane * 16;

    uint32_t szc[8], szn[8];

    auto load_raw = [&](int w, int slot) {
        if (w < w1) {
            const int g  = w & (NG - 1);
            const int nbk = (w >> 6) << 6;
            const char* src = (const char*)(qw + (size_t)(nbk + rrow) * K_IN + g * BK) + ru0 * 16;
            const uint32_t dst = rawb + slot * RAWSTG + rrow * 512 + ru0 * 16;
            #pragma unroll
            for (int j = 0; j < 8; ++j)
                cp16(dst + j * 16, src + j * 16);
        }
        asm volatile("cp.async.commit_group;");
    };
    auto load_x = [&](int w, int slot) {
        if (w < w1) {
            const int g = w & (NG - 1);
            const __half* src = g_xh + (size_t)xrow * K_IN + g * BK;
            const uint32_t dstrow = asb + slot * ASTG + xrow * 256;
            #pragma unroll
            for (int j = 0; j < 4; ++j) {
                const int u = xu0 + j;
                cp16(dstrow + ((u ^ (xrow & 7)) << 4), src + u * 8);
            }
        }
        asm volatile("cp.async.commit_group;");
    };
    auto load_sz = [&](int w, uint32_t* dstreg) {
        const int g = w & (NG - 1);
        const int nbk = (w >> 6) << 6;
        const uint32_t* szp = g_szp + (size_t)g * N_OUT + nbk + warp;
        #pragma unroll
        for (int it = 0; it < 8; ++it)
            dstreg[it] = szp[it * 8];
    };

    // ---- prologue ----
    // G1 = {x(w0), raw(w0)}  (commit inside load_raw)
    {
        const int g = w0 & (NG - 1);
        const __half* src = g_xh + (size_t)xrow * K_IN + g * BK;
        const uint32_t dstrow = asb + xrow * 256;
        #pragma unroll
        for (int j = 0; j < 4; ++j) {
            const int u = xu0 + j;
            cp16(dstrow + ((u ^ (xrow & 7)) << 4), src + u * 8);
        }
    }
    load_raw(w0, 0);          // commits G1
    load_raw(w0 + 1, 1);      // commits G2
    load_sz(w0, szc);

    const __half2 k1032 = __floats2half2_rn(1032.f, 1032.f);
    int seg = 0;

    for (int w = w0; w < w1; ++w) {
        const int slot = (w - w0) & 1;
        asm volatile("cp.async.wait_group 1;");
        __syncthreads();   // raw/x(w) visible to all; MMA(w-1) done with Bs

        // ---- dequant: LDS raw -> fp16 Bs ----
        const uint32_t db = d_base + slot * RAWSTG;
        #pragma unroll
        for (int it = 0; it < 8; ++it) {
            const int nloc = it * 8 + warp;
            uint4 q;
            lds128(q, db + it * (8 * 512));
            const __half2 szh = *reinterpret_cast<const __half2*>(&szc[it]);
            const __half2 s2 = __half2half2(__low2half(szh));
            const __half2 z2 = __half2half2(__high2half(szh));
            uint32_t p0 = 0x64006400u | q.x | (q.y << 16);
            uint32_t p1 = 0x64006400u | q.z | (q.w << 16);
            __half2 h0 = __hsub2(*reinterpret_cast<const __half2*>(&p0), k1032);
            __half2 h1 = __hsub2(*reinterpret_cast<const __half2*>(&p1), k1032);
            __half2 w0h = __hfma2(h0, s2, z2);
            __half2 w1h = __hfma2(h1, s2, z2);
            uint2 pk;
            pk.x = *reinterpret_cast<uint32_t*>(&w0h);
            pk.y = *reinterpret_cast<uint32_t*>(&w1h);
            *reinterpret_cast<uint2*>(&Bs[nloc * LDK + lane * 4]) = pk;
        }
        __syncthreads();   // publish Bs; raw[slot] now free

        // ---- issue next async loads (deep lookahead) ----
        load_x(w + 1, slot ^ 1);   // used at MMA(w+1): 1 chunk of cover (L2 source)
        load_raw(w + 2, slot);     // used at dequant(w+2): >1.3 chunks of cover (DRAM)
        if (w + 1 < w1) load_sz(w + 1, szn);

        // ---- MMA ----
        const uint32_t ar = a_rowb + slot * ASTG;
        #pragma unroll
        for (int kk = 0; kk < 8; ++kk) {
            uint32_t a0, a1, a2, a3;
            ldsm4(a0, a1, a2, a3, ar + (((kk * 2 + a_hi) ^ a_sw) << 4));
            uint32_t b0, b1, b2, b3, b4, b5, b6, b7;
            ldsm4(b0, b1, b2, b3, b_off0 + kk * 32);
            ldsm4(b4, b5, b6, b7, b_off1 + kk * 32);
            mma_16816(acc[0], a0, a1, a2, a3, b0, b1);
            mma_16816(acc[1], a0, a1, a2, a3, b2, b3);
            mma_16816(acc[2], a0, a1, a2, a3, b4, b5);
            mma_16816(acc[3], a0, a1, a2, a3, b6, b7);
        }

        #pragma unroll
        for (int it = 0; it < 8; ++it) szc[it] = szn[it];

        // ---- segment boundary: write partial 64x64 block ----
        if (w + 1 == w1 || ((w + 1) >> 6) != (w >> 6)) {
            float* part = g_part + ((size_t)cta * 2 + seg) * 4096;
            const int row = wm * 16 + (lane >> 2);
            #pragma unroll
            for (int j = 0; j < 4; ++j) {
                const int col = wn * 32 + j * 8 + (lane & 3) * 2;
                *reinterpret_cast<float2*>(part + row * 64 + col) =
                    make_float2(acc[j][0], acc[j][1]);
                *reinterpret_cast<float2*>(part + (row + 8) * 64 + col) =
                    make_float2(acc[j][2], acc[j][3]);
                acc[j][0] = acc[j][1] = acc[j][2] = acc[j][3] = 0.f;
            }
            ++seg;
        }
    }
}

extern "C" void kernel_launch(void* const* d_in, const int* in_sizes, int n_in,
                              void* d_out, int out_size) {
    const float* x  = (const float*)d_in[0];   // (64, 8192) fp32
    const int*   qw = (const int*)d_in[1];     // (8192, 8192) int32 in [0,15]
    const float* sz = (const float*)d_in[2];   // (64, 8192, 2) fp32
    float* out = (float*)d_out;                // (64, 8192) fp32

    static bool attr_set = false;
    if (!attr_set) {
        cudaFuncSetAttribute(woq_gemm_kernel,
                             cudaFuncAttributeMaxDynamicSharedMemorySize, SMEM_BYTES);
        attr_set = true;
    }

    const int n_prep = (M_TOK * K_IN / 8) + (NG * N_OUT / 4);
    prep_kernel<<<n_prep / 256, 256>>>(x, sz);
    woq_gemm_kernel<<<NCTA, NTHREADS, SMEM_BYTES>>>(qw);
    reduce_kernel<<<(M_TOK * N_OUT / 2) / 256, 256>>>(out);
}

// round 11
// speedup vs baseline: 1.1271x; 1.1271x over previous
#include <cuda_runtime.h>
#include <cuda_fp16.h>
#include <cstdint>

#define M_TOK 64
#define N_OUT 8192
#define K_IN  8192
#define NG    64            // K groups per row (8192/128)
#define NTILES (N_OUT / 64) // 128
#define WTOTAL (NTILES * NG)// 8192 work units
#define NCTA  296           // 2 per SM on 148 SMs
#define BN    64
#define BK    128
#define LDK   136
#define NTHREADS 256
#define ABYTES (M_TOK * LDK * 2)
#define BBYTES (BN * LDK * 2)
#define SMEM_BYTES (2 * ABYTES + 2 * BBYTES)  // 69632 B -> 2 CTA/SM

#define KB2   (K_IN / 2)    // packed bytes per row = 4096

__device__ __half   g_xh[M_TOK * K_IN];      // x in fp16 (1 MB)
__device__ uint32_t g_szp[NG * N_OUT];       // packed (s,z) half2 (2 MB)
__device__ uint8_t  g_wp[(size_t)N_OUT * KB2];  // nibble-packed weights (32 MB)
__device__ float    g_part[NCTA * 2 * 4096]; // stream-K partials

__device__ __forceinline__ int gsplit(int c) { return (int)(((long long)c * WTOTAL) / NCTA); }

// ---- pack: qw int32 -> nibbles (2q/byte); also converts x and packs sz ----
// work items: NP = 67108864/16 pack units (16 q -> 8 B), then x (8 f/thr), then sz.
#define NP (N_OUT * K_IN / 16)     // 4194304
#define NXT (M_TOK * K_IN / 8)     // 65536
#define NST (NG * N_OUT / 4)       // 131072
#define PACK_THREADS ((NP + NXT + NST) / 256)  // 17152 blocks of 256

__global__ void pack_kernel(const int* __restrict__ qw,
                            const float* __restrict__ x,
                            const float* __restrict__ sz) {
    int t = blockIdx.x * blockDim.x + threadIdx.x;
    if (t < NP) {
        const int4* src = reinterpret_cast<const int4*>(qw) + (size_t)t * 4;
        int4 v0 = src[0];
        int4 v1 = src[1];
        int4 v2 = src[2];
        int4 v3 = src[3];
        uint32_t a = (uint32_t)v0.x | ((uint32_t)v0.y << 4) | ((uint32_t)v0.z << 8)  |
                     ((uint32_t)v0.w << 12) | ((uint32_t)v1.x << 16) |
                     ((uint32_t)v1.y << 20) | ((uint32_t)v1.z << 24) | ((uint32_t)v1.w << 28);
        uint32_t b = (uint32_t)v2.x | ((uint32_t)v2.y << 4) | ((uint32_t)v2.z << 8)  |
                     ((uint32_t)v2.w << 12) | ((uint32_t)v3.x << 16) |
                     ((uint32_t)v3.y << 20) | ((uint32_t)v3.z << 24) | ((uint32_t)v3.w << 28);
        uint2 pk = make_uint2(a, b);
        *reinterpret_cast<uint2*>(g_wp + (size_t)t * 8) = pk;
    } else if (t < NP + NXT) {
        int u = t - NP;
        float4 v0 = *reinterpret_cast<const float4*>(x + (size_t)u * 8);
        float4 v1 = *reinterpret_cast<const float4*>(x + (size_t)u * 8 + 4);
        __half2 h0 = __floats2half2_rn(v0.x, v0.y);
        __half2 h1 = __floats2half2_rn(v0.z, v0.w);
        __half2 h2 = __floats2half2_rn(v1.x, v1.y);
        __half2 h3 = __floats2half2_rn(v1.z, v1.w);
        uint4 pk;
        pk.x = *reinterpret_cast<uint32_t*>(&h0);
        pk.y = *reinterpret_cast<uint32_t*>(&h1);
        pk.z = *reinterpret_cast<uint32_t*>(&h2);
        pk.w = *reinterpret_cast<uint32_t*>(&h3);
        *reinterpret_cast<uint4*>(g_xh + (size_t)u * 8) = pk;
    } else {
        int u = t - NP - NXT;
        float4 v0 = *reinterpret_cast<const float4*>(sz + (size_t)u * 8);
        float4 v1 = *reinterpret_cast<const float4*>(sz + (size_t)u * 8 + 4);
        __half2 a = __floats2half2_rn(v0.x, v0.y);
        __half2 b = __floats2half2_rn(v0.z, v0.w);
        __half2 c2 = __floats2half2_rn(v1.x, v1.y);
        __half2 d = __floats2half2_rn(v1.z, v1.w);
        uint4 pk;
        pk.x = *reinterpret_cast<uint32_t*>(&a);
        pk.y = *reinterpret_cast<uint32_t*>(&b);
        pk.z = *reinterpret_cast<uint32_t*>(&c2);
        pk.w = *reinterpret_cast<uint32_t*>(&d);
        *reinterpret_cast<uint4*>(g_szp + (size_t)u * 4) = pk;
    }
}

// ---- stream-K reduce ----
__global__ void reduce_kernel(float* __restrict__ out) {
    int i2 = (blockIdx.x * blockDim.x + threadIdx.x) * 2;
    int m  = i2 >> 13;
    int n  = i2 & (N_OUT - 1);
    int nt = n >> 6, nl = n & 63;
    int X  = nt << 6;
    int c  = (int)(((long long)X * NCTA) >> 13);
    while (gsplit(c + 1) <= X) ++c;
    float sx = 0.f, sy = 0.f;
    while (c < NCTA && gsplit(c) < X + 64) {
        int seg = ((gsplit(c) >> 6) == nt) ? 0 : 1;
        const float2 v = *reinterpret_cast<const float2*>(
            g_part + ((size_t)c * 2 + seg) * 4096 + m * 64 + nl);
        sx += v.x; sy += v.y;
        ++c;
    }
    *reinterpret_cast<float2*>(out + i2) = make_float2(sx, sy);
}

__device__ __forceinline__ void cp16(uint32_t dst, const void* src) {
    asm volatile("cp.async.cg.shared.global [%0], [%1], 16;" :: "r"(dst), "l"(src));
}
__device__ __forceinline__ void ldsm4(uint32_t& r0, uint32_t& r1, uint32_t& r2, uint32_t& r3,
                                      uint32_t a) {
    asm volatile("ldmatrix.sync.aligned.m8n8.x4.shared.b16 {%0,%1,%2,%3}, [%4];"
                 : "=r"(r0), "=r"(r1), "=r"(r2), "=r"(r3) : "r"(a));
}
__device__ __forceinline__ void mma_16816(float c[4],
                                          uint32_t a0, uint32_t a1, uint32_t a2, uint32_t a3,
                                          uint32_t b0, uint32_t b1) {
    asm volatile("mma.sync.aligned.m16n8k16.row.col.f32.f16.f16.f32 "
                 "{%0,%1,%2,%3}, {%4,%5,%6,%7}, {%8,%9}, {%0,%1,%2,%3};"
                 : "+f"(c[0]), "+f"(c[1]), "+f"(c[2]), "+f"(c[3])
                 : "r"(a0), "r"(a1), "r"(a2), "r"(a3), "r"(b0), "r"(b1));
}

__global__ void __launch_bounds__(NTHREADS, 2)
woq_gemm_kernel()
{
    extern __shared__ __half smem[];
    __half* Bs = smem + 2 * M_TOK * LDK;

    const int tid  = threadIdx.x;
    const int lane = tid & 31;
    const int warp = tid >> 5;
    const int wm   = warp & 3;
    const int wn   = warp >> 2;
    const int cta  = blockIdx.x;

    const int w0 = gsplit(cta);
    const int w1 = gsplit(cta + 1);

    float acc[4][4];
    #pragma unroll
    for (int i = 0; i < 4; ++i)
        #pragma unroll
        for (int j = 0; j < 4; ++j) acc[i][j] = 0.f;

    const uint32_t s_base = (uint32_t)__cvta_generic_to_shared(smem);
    const uint32_t as_b = s_base;
    const uint32_t bs_b = s_base + 2 * ABYTES;

    const uint32_t a_off  = as_b + 2u * ((wm * 16 + (lane & 15)) * LDK + (lane >> 4) * 8);
    const uint32_t b_off0 = bs_b + 2u * ((wn * 32 + (lane & 7) + ((lane >> 4) << 3)) * LDK
                                         + ((lane >> 3) & 1) * 8);
    const uint32_t b_off1 = b_off0 + 2u * 16 * LDK;

    const int xrow0 = tid >> 4;
    const int xcol  = tid & 15;
    const __half* xsrc = g_xh + (size_t)xrow0 * K_IN + xcol * 8;
    const uint32_t adst = as_b + 2u * (xrow0 * LDK + xcol * 8);

    // this thread's two dequant rows (within the 64-row tile)
    const int r0 = (((lane >> 3) << 3)) + warp;       // rows warp + 8*(lane>>3)  (0..31 group)
    const int r1 = r0 + 32;                           // l=1: +4 steps of 8
    const int bcol = (lane & 7) * 8;                  // byte offset of this lane's 16-q segment

    uint2    wq8[2];   // packed weights: 16 q per row, 2 rows
    uint32_t szr[2];

    auto load_chunk = [&](int w, int pbuf) {
        const int g  = w & (NG - 1);
        const int nb = (w >> 6) << 6;
        const int k0 = g * BK;
        #pragma unroll
        for (int j = 0; j < 4; ++j)
            cp16(adst + pbuf * ABYTES + j * (16 * LDK * 2), xsrc + (size_t)j * 16 * K_IN + k0);
        asm volatile("cp.async.commit_group;");
        const uint8_t* base = g_wp + (size_t)nb * KB2 + g * 64 + bcol;
        wq8[0] = *reinterpret_cast<const uint2*>(base + (size_t)r0 * KB2);
        wq8[1] = *reinterpret_cast<const uint2*>(base + (size_t)r1 * KB2);
        szr[0] = g_szp[(size_t)g * N_OUT + nb + r0];
        szr[1] = g_szp[(size_t)g * N_OUT + nb + r1];
    };

    load_chunk(w0, 0);

    const __half2 k1032 = __floats2half2_rn(1032.f, 1032.f);
    int seg = 0;

    for (int w = w0; w < w1; ++w) {
        const int p = (w - w0) & 1;
        asm volatile("cp.async.wait_group 0;");

        // ---- dequant packed nibbles -> fp16 Bs[p] ----
        __half* Bsb = Bs + p * (BN * LDK);
        #pragma unroll
        for (int l = 0; l < 2; ++l) {
            const int row = l ? r1 : r0;
            const __half2 szh = *reinterpret_cast<const __half2*>(&szr[l]);
            const __half2 s2 = __half2half2(__low2half(szh));
            const __half2 z2 = __half2half2(__high2half(szh));
            uint32_t vv[2] = { wq8[l].x, wq8[l].y };
            uint32_t P[8];
            #pragma unroll
            for (int t2 = 0; t2 < 2; ++t2) {
                const uint32_t v = vv[t2];
                #pragma unroll
                for (int j = 0; j < 4; ++j) {
                    const uint32_t b = (v >> (8 * j)) & 0xFFu;
                    uint32_t pr = 0x64006400u | (b & 0xFu) | ((b & 0xF0u) << 12);
                    __half2 h = __hsub2(*reinterpret_cast<const __half2*>(&pr), k1032);
                    __half2 wv = __hfma2(h, s2, z2);
                    P[t2 * 4 + j] = *reinterpret_cast<uint32_t*>(&wv);
                }
            }
            __half* dst = Bsb + row * LDK + (lane & 7) * 16;
            *reinterpret_cast<uint4*>(dst)     = make_uint4(P[0], P[1], P[2], P[3]);
            *reinterpret_cast<uint4*>(dst + 8) = make_uint4(P[4], P[5], P[6], P[7]);
        }
        __syncthreads();

        // ---- prefetch chunk w+1 (overlaps MMA) ----
        if (w + 1 < w1)
            load_chunk(w + 1, p ^ 1);

        // ---- MMA ----
        const uint32_t ab  = a_off  + p * ABYTES;
        const uint32_t bb0 = b_off0 + p * BBYTES;
        const uint32_t bb1 = b_off1 + p * BBYTES;
        #pragma unroll
        for (int kk = 0; kk < 8; ++kk) {
            uint32_t a0, a1, a2, a3;
            ldsm4(a0, a1, a2, a3, ab + kk * 32);
            uint32_t b0, b1, b2, b3, b4, b5, b6, b7;
            ldsm4(b0, b1, b2, b3, bb0 + kk * 32);
            ldsm4(b4, b5, b6, b7, bb1 + kk * 32);
            mma_16816(acc[0], a0, a1, a2, a3, b0, b1);
            mma_16816(acc[1], a0, a1, a2, a3, b2, b3);
            mma_16816(acc[2], a0, a1, a2, a3, b4, b5);
            mma_16816(acc[3], a0, a1, a2, a3, b6, b7);
        }

        // ---- segment boundary: write partial 64x64 block ----
        if (w + 1 == w1 || ((w + 1) >> 6) != (w >> 6)) {
            float* part = g_part + ((size_t)cta * 2 + seg) * 4096;
            const int row = wm * 16 + (lane >> 2);
            #pragma unroll
            for (int j = 0; j < 4; ++j) {
                const int col = wn * 32 + j * 8 + (lane & 3) * 2;
                *reinterpret_cast<float2*>(part + row * 64 + col) =
                    make_float2(acc[j][0], acc[j][1]);
                *reinterpret_cast<float2*>(part + (row + 8) * 64 + col) =
                    make_float2(acc[j][2], acc[j][3]);
                acc[j][0] = acc[j][1] = acc[j][2] = acc[j][3] = 0.f;
            }
            ++seg;
        }
    }
}

extern "C" void kernel_launch(void* const* d_in, const int* in_sizes, int n_in,
                              void* d_out, int out_size) {
    const float* x  = (const float*)d_in[0];   // (64, 8192) fp32
    const int*   qw = (const int*)d_in[1];     // (8192, 8192) int32 in [0,15]
    const float* sz = (const float*)d_in[2];   // (64, 8192, 2) fp32
    float* out = (float*)d_out;                // (64, 8192) fp32

    static bool attr_set = false;
    if (!attr_set) {
        cudaFuncSetAttribute(woq_gemm_kernel,
                             cudaFuncAttributeMaxDynamicSharedMemorySize, SMEM_BYTES);
        attr_set = true;
    }

    pack_kernel<<<PACK_THREADS, 256>>>(qw, x, sz);
    woq_gemm_kernel<<<NCTA, NTHREADS, SMEM_BYTES>>>();
    reduce_kernel<<<(M_TOK * N_OUT / 2) / 256, 256>>>(out);
}

// round 13
// speedup vs baseline: 1.7384x; 1.5423x over previous
#include <cuda_runtime.h>
#include <cuda_fp16.h>
#include <cstdint>

#define M_TOK 64
#define N_OUT 8192
#define K_IN  8192
#define NG    64            // K groups per row (8192/128)
#define NTILES (N_OUT / 64) // 128
#define WTOTAL (NTILES * NG)// 8192 work units
#define NCTA  296           // 2 per SM on 148 SMs, all resident
#define BN    64
#define BK    128
#define LDK   136
#define NTHREADS 256
#define ABYTES (M_TOK * LDK * 2)
#define BBYTES (BN * LDK * 2)
#define SMEM_BYTES (2 * ABYTES + 2 * BBYTES)  // 69632 B -> 2 CTA/SM

__device__ __half   g_xh[M_TOK * K_IN];      // x in fp16 (1 MB)
__device__ uint32_t g_szp[NG * N_OUT];       // packed (s,z) half2 (2 MB)
__device__ float    g_part[NCTA * 2 * 4096]; // stream-K partials

__device__ __forceinline__ int gsplit(int c) { return (int)(((long long)c * WTOTAL) / NCTA); }

// ---- prep: convert x to fp16 + pack (s,z) to half2; 16 floats/thread ----
__global__ void prep_kernel(const float* __restrict__ x, const float* __restrict__ sz) {
    const int NX = M_TOK * K_IN / 16;   // 32768 threads for x
    int t = blockIdx.x * blockDim.x + threadIdx.x;
    const float* src = (t < NX) ? (x + (size_t)t * 16)
                                : (sz + (size_t)(t - NX) * 16);
    uint32_t* dst = (t < NX) ? reinterpret_cast<uint32_t*>(g_xh + (size_t)t * 16)
                             : (g_szp + (size_t)(t - NX) * 8);
    float4 v0 = *reinterpret_cast<const float4*>(src);
    float4 v1 = *reinterpret_cast<const float4*>(src + 4);
    float4 v2 = *reinterpret_cast<const float4*>(src + 8);
    float4 v3 = *reinterpret_cast<const float4*>(src + 12);
    __half2 h0 = __floats2half2_rn(v0.x, v0.y);
    __half2 h1 = __floats2half2_rn(v0.z, v0.w);
    __half2 h2 = __floats2half2_rn(v1.x, v1.y);
    __half2 h3 = __floats2half2_rn(v1.z, v1.w);
    __half2 h4 = __floats2half2_rn(v2.x, v2.y);
    __half2 h5 = __floats2half2_rn(v2.z, v2.w);
    __half2 h6 = __floats2half2_rn(v3.x, v3.y);
    __half2 h7 = __floats2half2_rn(v3.z, v3.w);
    uint4 pa, pb;
    pa.x = *reinterpret_cast<uint32_t*>(&h0);
    pa.y = *reinterpret_cast<uint32_t*>(&h1);
    pa.z = *reinterpret_cast<uint32_t*>(&h2);
    pa.w = *reinterpret_cast<uint32_t*>(&h3);
    pb.x = *reinterpret_cast<uint32_t*>(&h4);
    pb.y = *reinterpret_cast<uint32_t*>(&h5);
    pb.z = *reinterpret_cast<uint32_t*>(&h6);
    pb.w = *reinterpret_cast<uint32_t*>(&h7);
    *reinterpret_cast<uint4*>(dst)     = pa;
    *reinterpret_cast<uint4*>(dst + 4) = pb;
}

// ---- stream-K reduce ----
__global__ void reduce_kernel(float* __restrict__ out) {
    int i2 = (blockIdx.x * blockDim.x + threadIdx.x) * 2;
    int m  = i2 >> 13;
    int n  = i2 & (N_OUT - 1);
    int nt = n >> 6, nl = n & 63;
    int X  = nt << 6;
    int c  = (int)(((long long)X * NCTA) >> 13);
    while (gsplit(c + 1) <= X) ++c;
    float sx = 0.f, sy = 0.f;
    while (c < NCTA && gsplit(c) < X + 64) {
        int seg = ((gsplit(c) >> 6) == nt) ? 0 : 1;
        const float2 v = *reinterpret_cast<const float2*>(
            g_part + ((size_t)c * 2 + seg) * 4096 + m * 64 + nl);
        sx += v.x; sy += v.y;
        ++c;
    }
    *reinterpret_cast<float2*>(out + i2) = make_float2(sx, sy);
}

__device__ __forceinline__ void cp16(uint32_t dst, const void* src) {
    asm volatile("cp.async.cg.shared.global [%0], [%1], 16;" :: "r"(dst), "l"(src));
}
__device__ __forceinline__ void ldsm4(uint32_t& r0, uint32_t& r1, uint32_t& r2, uint32_t& r3,
                                      uint32_t a) {
    asm volatile("ldmatrix.sync.aligned.m8n8.x4.shared.b16 {%0,%1,%2,%3}, [%4];"
                 : "=r"(r0), "=r"(r1), "=r"(r2), "=r"(r3) : "r"(a));
}
__device__ __forceinline__ void mma_16816(float c[4],
                                          uint32_t a0, uint32_t a1, uint32_t a2, uint32_t a3,
                                          uint32_t b0, uint32_t b1) {
    asm volatile("mma.sync.aligned.m16n8k16.row.col.f32.f16.f16.f32 "
                 "{%0,%1,%2,%3}, {%4,%5,%6,%7}, {%8,%9}, {%0,%1,%2,%3};"
                 : "+f"(c[0]), "+f"(c[1]), "+f"(c[2]), "+f"(c[3])
                 : "r"(a0), "r"(a1), "r"(a2), "r"(a3), "r"(b0), "r"(b1));
}

__global__ void __launch_bounds__(NTHREADS, 2)
woq_gemm_kernel(const int* __restrict__ qw)
{
    extern __shared__ __half smem[];
    __half* Bs = smem + 2 * M_TOK * LDK;

    const int tid  = threadIdx.x;
    const int lane = tid & 31;
    const int warp = tid >> 5;
    const int wm   = warp & 3;
    const int wn   = warp >> 2;
    const int cta  = blockIdx.x;

    const int w0 = gsplit(cta);
    const int w1 = gsplit(cta + 1);

    float acc[4][4];
    #pragma unroll
    for (int i = 0; i < 4; ++i)
        #pragma unroll
        for (int j = 0; j < 4; ++j) acc[i][j] = 0.f;

    const uint32_t s_base = (uint32_t)__cvta_generic_to_shared(smem);
    const uint32_t as_b = s_base;
    const uint32_t bs_b = s_base + 2 * ABYTES;

    const uint32_t a_off  = as_b + 2u * ((wm * 16 + (lane & 15)) * LDK + (lane >> 4) * 8);
    const uint32_t b_off0 = bs_b + 2u * ((wn * 32 + (lane & 7) + ((lane >> 4) << 3)) * LDK
                                         + ((lane >> 3) & 1) * 8);
    const uint32_t b_off1 = b_off0 + 2u * 16 * LDK;

    const int xrow0 = tid >> 4;
    const int xcol  = tid & 15;
    const __half* xsrc = g_xh + (size_t)xrow0 * K_IN + xcol * 8;
    const uint32_t adst = as_b + 2u * (xrow0 * LDK + xcol * 8);

    int4     wq[8];    // staged weights for the CURRENT chunk
    uint32_t szr[8];   // staged packed (s,z) for the CURRENT chunk

    // per-thread fixed offsets
    const int*      qbase  = qw + (size_t)warp * K_IN + lane * 4;
    const uint32_t* szbase = g_szp + warp;

    // ---- prologue: fill regs for chunk w0, start As(w0) ----
    {
        const int g  = w0 & (NG - 1);
        const int nb = (w0 >> 6) << 6;
        const int k0 = g * BK;
        #pragma unroll
        for (int j = 0; j < 4; ++j)
            cp16(adst + j * (16 * LDK * 2), xsrc + (size_t)j * 16 * K_IN + k0);
        asm volatile("cp.async.commit_group;");
        const int* qr = qbase + (size_t)nb * K_IN + k0;
        #pragma unroll
        for (int it = 0; it < 8; ++it)
            wq[it] = *reinterpret_cast<const int4*>(qr + (size_t)(it * 8) * K_IN);
        const uint32_t* szp = szbase + (size_t)g * N_OUT + nb;
        #pragma unroll
        for (int it = 0; it < 8; ++it)
            szr[it] = szp[it * 8];
    }

    const __half2 k1032 = __floats2half2_rn(1032.f, 1032.f);
    int seg = 0;

    for (int w = w0; w < w1; ++w) {
        const int p = (w - w0) & 1;

        // next-chunk addresses (clamped to w on the last chunk: harmless reload)
        const int wn_ = (w + 1 < w1) ? (w + 1) : w;
        const int gN  = wn_ & (NG - 1);
        const int nbN = (wn_ >> 6) << 6;
        const int* qrN = qbase + (size_t)nbN * K_IN + gN * BK;
        const uint32_t* szpN = szbase + (size_t)gN * N_OUT + nbN;

        asm volatile("cp.async.wait_group 0;");

        // ---- dequant chunk w -> Bs[p], interleaving next-chunk LDG issue.
        // wq[it]/szr[it] are consumed at iteration it and refilled immediately:
        // the w+1 DRAM loads get dequant-rest + barrier + MMA + barrier of cover.
        __half* Bsb = Bs + p * (BN * LDK);
        #pragma unroll
        for (int it = 0; it < 8; ++it) {
            const int4     q   = wq[it];
            const uint32_t szv = szr[it];
            wq[it]  = *reinterpret_cast<const int4*>(qrN + (size_t)(it * 8) * K_IN);
            szr[it] = szpN[it * 8];
            const int nloc = it * 8 + warp;
            const __half2 szh = *reinterpret_cast<const __half2*>(&szv);
            const __half2 s2 = __half2half2(__low2half(szh));
            const __half2 z2 = __half2half2(__high2half(szh));
            uint32_t p0 = 0x64006400u | (uint32_t)q.x | ((uint32_t)q.y << 16);
            uint32_t p1 = 0x64006400u | (uint32_t)q.z | ((uint32_t)q.w << 16);
            __half2 h0 = __hsub2(*reinterpret_cast<const __half2*>(&p0), k1032);
            __half2 h1 = __hsub2(*reinterpret_cast<const __half2*>(&p1), k1032);
            __half2 w0h = __hfma2(h0, s2, z2);
            __half2 w1h = __hfma2(h1, s2, z2);
            uint2 pk;
            pk.x = *reinterpret_cast<uint32_t*>(&w0h);
            pk.y = *reinterpret_cast<uint32_t*>(&w1h);
            *reinterpret_cast<uint2*>(&Bsb[nloc * LDK + lane * 4]) = pk;
        }
        __syncthreads();   // Bs[p] published; all warps done with MMA(w-1)

        // ---- issue As(w+1) into the freed buffer ----
        if (w + 1 < w1) {
            const int k0N = gN * BK;
            #pragma unroll
            for (int j = 0; j < 4; ++j)
                cp16(adst + (p ^ 1) * ABYTES + j * (16 * LDK * 2),
                     xsrc + (size_t)j * 16 * K_IN + k0N);
        }
        asm volatile("cp.async.commit_group;");

        // ---- MMA ----
        const uint32_t ab  = a_off  + p * ABYTES;
        const uint32_t bb0 = b_off0 + p * BBYTES;
        const uint32_t bb1 = b_off1 + p * BBYTES;
        #pragma unroll
        for (int kk = 0; kk < 8; ++kk) {
            uint32_t a0, a1, a2, a3;
            ldsm4(a0, a1, a2, a3, ab + kk * 32);
            uint32_t b0, b1, b2, b3, b4, b5, b6, b7;
            ldsm4(b0, b1, b2, b3, bb0 + kk * 32);
            ldsm4(b4, b5, b6, b7, bb1 + kk * 32);
            mma_16816(acc[0], a0, a1, a2, a3, b0, b1);
            mma_16816(acc[1], a0, a1, a2, a3, b2, b3);
            mma_16816(acc[2], a0, a1, a2, a3, b4, b5);
            mma_16816(acc[3], a0, a1, a2, a3, b6, b7);
        }

        // ---- segment boundary: write partial 64x64 block ----
        if (w + 1 == w1 || ((w + 1) >> 6) != (w >> 6)) {
            float* part = g_part + ((size_t)cta * 2 + seg) * 4096;
            const int row = wm * 16 + (lane >> 2);
            #pragma unroll
            for (int j = 0; j < 4; ++j) {
                const int col = wn * 32 + j * 8 + (lane & 3) * 2;
                *reinterpret_cast<float2*>(part + row * 64 + col) =
                    make_float2(acc[j][0], acc[j][1]);
                *reinterpret_cast<float2*>(part + (row + 8) * 64 + col) =
                    make_float2(acc[j][2], acc[j][3]);
                acc[j][0] = acc[j][1] = acc[j][2] = acc[j][3] = 0.f;
            }
            ++seg;
        }
    }
}

extern "C" void kernel_launch(void* const* d_in, const int* in_sizes, int n_in,
                              void* d_out, int out_size) {
    const float* x  = (const float*)d_in[0];   // (64, 8192) fp32
    const int*   qw = (const int*)d_in[1];     // (8192, 8192) int32 in [0,15]
    const float* sz = (const float*)d_in[2];   // (64, 8192, 2) fp32
    float* out = (float*)d_out;                // (64, 8192) fp32

    static bool attr_set = false;
    if (!attr_set) {
        cudaFuncSetAttribute(woq_gemm_kernel,
                             cudaFuncAttributeMaxDynamicSharedMemorySize, SMEM_BYTES);
        attr_set = true;
    }

    const int n_prep = (M_TOK * K_IN / 16) + (NG * N_OUT / 8);  // 98304 threads
    prep_kernel<<<n_prep / 256, 256>>>(x, sz);
    woq_gemm_kernel<<<NCTA, NTHREADS, SMEM_BYTES>>>(qw);
    reduce_kernel<<<(M_TOK * N_OUT / 2) / 256, 256>>>(out);
}